// round 7
// baseline (speedup 1.0000x reference)
#include <cuda_runtime.h>
#include <cuda_bf16.h>

#define Nb  8
#define Ssz 1024
#define Esz 1024
#define Hn  16
#define DKs 64
#define NSE (Nb*Ssz*Esz)                 // 8388608
#define NSE2 (NSE/2)
#define EE2 (Esz*Esz/2)
#define NHSS (134217728)
#define NROWS (Hn*Nb*Ssz)                // 131072

// Packed bf16 hi/lo planes (word i = pair (2i, 2i+1) along k)
__device__ unsigned g_Inh[NSE2], g_Inl[NSE2];
__device__ unsigned g_Qh[NSE2], g_Ql[NSE2];
__device__ unsigned g_Kh[NSE2], g_Kl[NSE2];
__device__ unsigned g_Vth[NSE2], g_Vtl[NSE2];      // [nh][d][t/2]
__device__ unsigned g_Oh[NSE2], g_Ol[NSE2];
__device__ unsigned g_Wth[4*EE2], g_Wtl[4*EE2];
__device__ float    g_Vt[NSE];
__device__ float    g_rowsum[NROWS];               // per (nh,row) sum of exp
__device__ float    g_attn_fb[NHSS];

#define CPA16(saddr, gptr) asm volatile("cp.async.cg.shared.global [%0], [%1], 16;\n" :: "r"(saddr), "l"(gptr))
#define CPCOMMIT() asm volatile("cp.async.commit_group;\n")
#define CPWAIT(n)  asm volatile("cp.async.wait_group %0;\n" :: "n"(n))

__device__ __forceinline__ void pack2(float x, float y, unsigned& h, unsigned& l) {
  __nv_bfloat162 hh = __float22bfloat162_rn(make_float2(x, y));
  float2 f = __bfloat1622float2(hh);
  __nv_bfloat162 ll = __float22bfloat162_rn(make_float2(x - f.x, y - f.y));
  h = *reinterpret_cast<unsigned*>(&hh);
  l = *reinterpret_cast<unsigned*>(&ll);
}

__device__ __forceinline__ void mma4(float* c, const unsigned* a, unsigned b0, unsigned b1) {
  asm volatile(
      "mma.sync.aligned.m16n8k16.row.col.f32.bf16.bf16.f32 "
      "{%0,%1,%2,%3}, {%4,%5,%6,%7}, {%8,%9}, {%0,%1,%2,%3};\n"
      : "+f"(c[0]), "+f"(c[1]), "+f"(c[2]), "+f"(c[3])
      : "r"(a[0]), "r"(a[1]), "r"(a[2]), "r"(a[3]), "r"(b0), "r"(b1));
}

template <int MT, int NT, int PITCH, int CH>
__device__ __forceinline__ void compute_tile2(
    const unsigned* Ah, const unsigned* Al, const unsigned* Bh, const unsigned* Bl,
    int wm0, int wn0, int gr, int q, float (&acc)[MT][NT][4]) {
#pragma unroll
  for (int c = 0; c < CH; c++) {
    unsigned ah[MT][4], al[MT][4];
#pragma unroll
    for (int mt = 0; mt < MT; mt++) {
      int r0 = (wm0 + 16*mt + gr)*PITCH + 8*c + q;
      int r1 = (wm0 + 16*mt + 8 + gr)*PITCH + 8*c + q;
      ah[mt][0]=Ah[r0]; ah[mt][1]=Ah[r1]; ah[mt][2]=Ah[r0+4]; ah[mt][3]=Ah[r1+4];
      al[mt][0]=Al[r0]; al[mt][1]=Al[r1]; al[mt][2]=Al[r0+4]; al[mt][3]=Al[r1+4];
    }
#pragma unroll
    for (int nt = 0; nt < NT; nt++) {
      int rb = (wn0 + 8*nt + gr)*PITCH + 8*c + q;
      unsigned bh0=Bh[rb], bh1=Bh[rb+4], bl0=Bl[rb], bl1=Bl[rb+4];
#pragma unroll
      for (int mt = 0; mt < MT; mt++) {
        mma4(acc[mt][nt], ah[mt], bh0, bh1);
        mma4(acc[mt][nt], ah[mt], bl0, bl1);
        mma4(acc[mt][nt], al[mt], bh0, bh1);
      }
    }
  }
}

__global__ void convert_pack(const float* __restrict__ src,
                             unsigned* __restrict__ h, unsigned* __restrict__ l, int npairs) {
  for (int i = blockIdx.x*blockDim.x + threadIdx.x; i < npairs; i += gridDim.x*blockDim.x) {
    float2 v = ((const float2*)src)[i];
    pack2(v.x, v.y, h[i], l[i]);
  }
}

__global__ __launch_bounds__(256) void transpose_convert(
    const float* __restrict__ W, unsigned* __restrict__ Th, unsigned* __restrict__ Tl) {
  __shared__ float tile[32][33];
  int bx = blockIdx.x*32, by = blockIdx.y*32;
  int t = threadIdx.x, x = t & 31, y = t >> 5;
#pragma unroll
  for (int i = 0; i < 4; i++)
    tile[y + 8*i][x] = W[(size_t)(by + y + 8*i)*1024 + bx + x];
  __syncthreads();
#pragma unroll
  for (int j = 0; j < 2; j++) {
    int idx = t + 256*j;
    int n = idx >> 4, p = idx & 15;
    unsigned h, l;
    pack2(tile[2*p][n], tile[2*p+1][n], h, l);
    Th[(size_t)(bx + n)*512 + (by >> 1) + p] = h;
    Tl[(size_t)(bx + n)*512 + (by >> 1) + p] = l;
  }
}

__device__ __forceinline__ void proj_issue(
    unsigned sbase, const unsigned* Ah_g, const unsigned* Al_g,
    const unsigned* Bh_g, const unsigned* Bl_g, int m0, int n0, int kt2, int tid) {
#pragma unroll
  for (int j = 0; j < 2; j++) {
    int c = tid + 256*j;
    int m = c >> 2, kc = c & 3;
    unsigned d = sbase + (unsigned)((m*20 + kc*4)*4);
    size_t ga = (size_t)m*512 + kt2 + kc*4;
    CPA16(d + 0u*10240u, Ah_g + (size_t)m0*512 + ga);
    CPA16(d + 1u*10240u, Al_g + (size_t)m0*512 + ga);
    CPA16(d + 2u*10240u, Bh_g + (size_t)n0*512 + ga);
    CPA16(d + 3u*10240u, Bl_g + (size_t)n0*512 + ga);
  }
}

// ---------------------------------------------------------------------------
// Projection GEMM from planes. EPI: 0=write planes, 1=write fp32, 2=write Vt fp32
// ---------------------------------------------------------------------------
template <int EPI>
__global__ __launch_bounds__(256, 2) void proj_mma(
    const unsigned* __restrict__ Ah_g, const unsigned* __restrict__ Al_g,
    const unsigned* __restrict__ Bh_g, const unsigned* __restrict__ Bl_g,
    const float* __restrict__ bias, float* __restrict__ Cf,
    unsigned* __restrict__ Ch, unsigned* __restrict__ Cl) {
  extern __shared__ unsigned sm[];
  const int tid = threadIdx.x, wid = tid >> 5, lane = tid & 31;
  const int gr = lane >> 2, q = lane & 3;
  const int wm0 = (wid >> 2)*64, wn0 = (wid & 3)*32;
  const int m0 = blockIdx.y*128, n0 = blockIdx.x*128;
  unsigned smu = (unsigned)__cvta_generic_to_shared(sm);
  float acc[4][4][4] = {};
  proj_issue(smu, Ah_g, Al_g, Bh_g, Bl_g, m0, n0, 0, tid);
  CPCOMMIT();
  for (int t = 0; t < 32; t++) {
    if (t + 1 < 32)
      proj_issue(smu + ((t+1)&1)*40960u, Ah_g, Al_g, Bh_g, Bl_g, m0, n0, (t+1)*16, tid);
    CPCOMMIT();
    CPWAIT(1);
    __syncthreads();
    const unsigned* base = sm + (t&1)*10240;
    compute_tile2<4,4,20,2>(base, base+2560, base+5120, base+7680, wm0, wn0, gr, q, acc);
    __syncthreads();
  }
#pragma unroll
  for (int mt = 0; mt < 4; mt++) {
#pragma unroll
    for (int nt = 0; nt < 4; nt++) {
      int row = m0 + wm0 + 16*mt + gr;
      int col = n0 + wn0 + 8*nt + 2*q;
      float b0 = bias[col], b1 = bias[col+1];
      float v0 = acc[mt][nt][0] + b0, v1 = acc[mt][nt][1] + b1;
      float v2 = acc[mt][nt][2] + b0, v3 = acc[mt][nt][3] + b1;
      if (EPI == 0) {
        int w = col >> 1;
        pack2(v0, v1, Ch[(size_t)row*512 + w], Cl[(size_t)row*512 + w]);
        pack2(v2, v3, Ch[(size_t)(row+8)*512 + w], Cl[(size_t)(row+8)*512 + w]);
      } else if (EPI == 1) {
        *(float2*)&Cf[(size_t)row*1024 + col] = make_float2(v0, v1);
        *(float2*)&Cf[(size_t)(row+8)*1024 + col] = make_float2(v2, v3);
      } else {
        int nb = row >> 10, s = row & 1023;
        int h = col >> 6, d = col & 63;
        float* p = Cf + (((size_t)(nb*16 + h))*64 + d)*1024 + s;
        p[0] = v0; p[1024] = v1; p[8] = v2; p[1024 + 8] = v3;
      }
    }
  }
}

// ---------------------------------------------------------------------------
// QK^T -> e = exp(masked/scaled logit) (max-free softmax numerator) + row sums.
// Same 128x128 CTA shape as R5. dyn smem 73728B.
// ---------------------------------------------------------------------------
__global__ __launch_bounds__(256, 2) void qk_mma(
    const int* __restrict__ mask, float* __restrict__ attn) {
  extern __shared__ unsigned sm[];
  const int tid = threadIdx.x, wid = tid >> 5, lane = tid & 31;
  const int gr = lane >> 2, q = lane & 3;
  const int wm0 = (wid >> 2)*64, wn0 = (wid & 3)*32;
  const int t0 = blockIdx.x*128, m0 = blockIdx.y*128;
  const int nh = blockIdx.z, nb = nh >> 4, h = nh & 15;
  unsigned smu = (unsigned)__cvta_generic_to_shared(sm);
  const size_t qoff = (size_t)(nb*1024 + m0)*512 + h*32;
  const size_t koff = (size_t)(nb*1024 + t0)*512 + h*32;
#pragma unroll
  for (int j = 0; j < 4; j++) {
    int c = tid + 256*j;
    int m = c >> 3, kc = c & 7;
    unsigned d = smu + (unsigned)((m*36 + kc*4)*4);
    size_t ga = (size_t)m*512 + kc*4;
    CPA16(d + 0u*18432u, g_Qh + qoff + ga);
    CPA16(d + 1u*18432u, g_Ql + qoff + ga);
    CPA16(d + 2u*18432u, g_Kh + koff + ga);
    CPA16(d + 3u*18432u, g_Kl + koff + ga);
  }
  CPCOMMIT();
  CPWAIT(0);
  __syncthreads();
  float acc[4][4][4] = {};
  compute_tile2<4,4,36,4>(sm, sm+4608, sm+9216, sm+13824, wm0, wn0, gr, q, acc);
  float rs[4][2] = {};
#pragma unroll
  for (int mt = 0; mt < 4; mt++) {
#pragma unroll
    for (int nt = 0; nt < 4; nt++) {
      int row = m0 + wm0 + 16*mt + gr;
      int t = t0 + wn0 + 8*nt + 2*q;
      int2 mA = *(const int2*)&mask[(size_t)(nb*1024 + row)*1024 + t];
      int2 mB = *(const int2*)&mask[(size_t)(nb*1024 + row + 8)*1024 + t];
      float2 v0, v1;
      v0.x = mA.x ? 0.f : __expf(acc[mt][nt][0]*0.125f);
      v0.y = mA.y ? 0.f : __expf(acc[mt][nt][1]*0.125f);
      v1.x = mB.x ? 0.f : __expf(acc[mt][nt][2]*0.125f);
      v1.y = mB.y ? 0.f : __expf(acc[mt][nt][3]*0.125f);
      rs[mt][0] += v0.x + v0.y;
      rs[mt][1] += v1.x + v1.y;
      *(float2*)&attn[((size_t)nh*1024 + row)*1024 + t] = v0;
      *(float2*)&attn[((size_t)nh*1024 + row + 8)*1024 + t] = v1;
    }
  }
  // quad reduce (lanes sharing same rows differ only in q = lane bits 0..1)
#pragma unroll
  for (int off = 1; off <= 2; off <<= 1) {
#pragma unroll
    for (int mt = 0; mt < 4; mt++) {
      rs[mt][0] += __shfl_xor_sync(0xffffffffu, rs[mt][0], off);
      rs[mt][1] += __shfl_xor_sync(0xffffffffu, rs[mt][1], off);
    }
  }
  if (q == 0) {
#pragma unroll
    for (int mt = 0; mt < 4; mt++) {
      int row = m0 + wm0 + 16*mt + gr;
      atomicAdd(&g_rowsum[(size_t)nh*1024 + row], rs[mt][0]);
      atomicAdd(&g_rowsum[(size_t)nh*1024 + row + 8], rs[mt][1]);
    }
  }
}

// ---------------------------------------------------------------------------
// Fused normalize + PV. Reads e, computes p = e/rowsum, writes p back in place
// (attn_weights output), splits p for MMA against Vt planes. Writes O planes.
// ---------------------------------------------------------------------------
__global__ __launch_bounds__(256, 2) void pv_mma(float* __restrict__ attn) {
  __shared__ unsigned Ah[2560], Al[2560], Bh[1280], Bl[1280];
  const int tid = threadIdx.x, wid = tid >> 5, lane = tid & 31;
  const int gr = lane >> 2, q = lane & 3;
  const int wm0 = (wid >> 2)*64, wn0 = (wid & 3)*16;
  const int m0 = blockIdx.x*128;
  const int nh = blockIdx.y, nb = nh >> 4, h = nh & 15;
  float* P = attn + (size_t)nh*1024*1024 + (size_t)m0*1024;
  float inv[4];
#pragma unroll
  for (int j = 0; j < 4; j++)
    inv[j] = 1.0f / g_rowsum[(size_t)nh*1024 + m0 + (tid >> 3) + 32*j];
  float acc[4][2][4] = {};
  for (int kt = 0; kt < 1024; kt += 32) {
#pragma unroll
    for (int j = 0; j < 4; j++) {
      int e = tid + 256*j;
      int m = e >> 3, kq = e & 7;
      float* gp = P + (size_t)m*1024 + kt + 4*kq;
      float4 v = *(const float4*)gp;
      float iv = inv[j];
      float4 p;
      p.x = v.x*iv; p.y = v.y*iv; p.z = v.z*iv; p.w = v.w*iv;
      *(float4*)gp = p;
      unsigned h01, h23, l01, l23;
      pack2(p.x, p.y, h01, l01);
      pack2(p.z, p.w, h23, l23);
      int base = m*20 + 2*kq;
      Ah[base]=h01; Ah[base+1]=h23; Al[base]=l01; Al[base+1]=l23;
    }
    {
      int m = tid >> 2, kc = tid & 3;
      if (m < 64) {
        size_t src = (size_t)(nh*64 + m)*512 + (kt >> 1) + kc*4;
        *(uint4*)&Bh[m*20 + kc*4] = *(const uint4*)&g_Vth[src];
        *(uint4*)&Bl[m*20 + kc*4] = *(const uint4*)&g_Vtl[src];
      }
    }
    __syncthreads();
    compute_tile2<4,2,20,2>(Ah, Al, Bh, Bl, wm0, wn0, gr, q, acc);
    __syncthreads();
  }
#pragma unroll
  for (int mt = 0; mt < 4; mt++) {
#pragma unroll
    for (int nt = 0; nt < 2; nt++) {
      int s = m0 + wm0 + 16*mt + gr;
      int col = h*64 + wn0 + 8*nt + 2*q;
      int w = col >> 1;
      size_t r0 = (size_t)(nb*1024 + s)*512 + w;
      size_t r1 = (size_t)(nb*1024 + s + 8)*512 + w;
      pack2(acc[mt][nt][0], acc[mt][nt][1], g_Oh[r0], g_Ol[r0]);
      pack2(acc[mt][nt][2], acc[mt][nt][3], g_Oh[r1], g_Ol[r1]);
    }
  }
}

// ---------------------------------------------------------------------------
extern "C" void kernel_launch(void* const* d_in, const int* in_sizes, int n_in,
                              void* d_out, int out_size) {
  const float* q  = (const float*)d_in[0];
  const float* k  = (const float*)d_in[1];
  const float* v  = (const float*)d_in[2];
  const int*   mask = (const int*)d_in[3];
  const float* wq = (const float*)d_in[4];
  const float* bq = (const float*)d_in[5];
  const float* wk = (const float*)d_in[6];
  const float* bk = (const float*)d_in[7];
  const float* wv = (const float*)d_in[8];
  const float* bv = (const float*)d_in[9];
  const float* wo = (const float*)d_in[10];
  const float* bo = (const float*)d_in[11];
  float* out = (float*)d_out;

  static bool attr_done = false;
  if (!attr_done) {
    cudaFuncSetAttribute(proj_mma<0>, cudaFuncAttributeMaxDynamicSharedMemorySize, 81920);
    cudaFuncSetAttribute(proj_mma<1>, cudaFuncAttributeMaxDynamicSharedMemorySize, 81920);
    cudaFuncSetAttribute(proj_mma<2>, cudaFuncAttributeMaxDynamicSharedMemorySize, 81920);
    cudaFuncSetAttribute(qk_mma, cudaFuncAttributeMaxDynamicSharedMemorySize, 73728);
    attr_done = true;
  }

  unsigned *Inh, *Inl, *Qh, *Ql, *Kh, *Kl, *Vth, *Vtl, *Oh, *Ol, *Wth, *Wtl;
  float *Vtp, *attn, *rowsum;
  cudaGetSymbolAddress((void**)&Inh, g_Inh);  cudaGetSymbolAddress((void**)&Inl, g_Inl);
  cudaGetSymbolAddress((void**)&Qh, g_Qh);    cudaGetSymbolAddress((void**)&Ql, g_Ql);
  cudaGetSymbolAddress((void**)&Kh, g_Kh);    cudaGetSymbolAddress((void**)&Kl, g_Kl);
  cudaGetSymbolAddress((void**)&Vth, g_Vth);  cudaGetSymbolAddress((void**)&Vtl, g_Vtl);
  cudaGetSymbolAddress((void**)&Oh, g_Oh);    cudaGetSymbolAddress((void**)&Ol, g_Ol);
  cudaGetSymbolAddress((void**)&Wth, g_Wth);  cudaGetSymbolAddress((void**)&Wtl, g_Wtl);
  cudaGetSymbolAddress((void**)&Vtp, g_Vt);
  cudaGetSymbolAddress((void**)&rowsum, g_rowsum);
  if ((long long)out_size >= (long long)NSE + (long long)NHSS) {
    attn = out + NSE;
  } else {
    cudaGetSymbolAddress((void**)&attn, g_attn_fb);
  }

  cudaMemsetAsync(rowsum, 0, NROWS*sizeof(float));

  dim3 tg(32, 32);
  transpose_convert<<<tg, 256>>>(wq, Wth + 0*EE2, Wtl + 0*EE2);
  transpose_convert<<<tg, 256>>>(wk, Wth + 1*EE2, Wtl + 1*EE2);
  transpose_convert<<<tg, 256>>>(wv, Wth + 2*EE2, Wtl + 2*EE2);
  transpose_convert<<<tg, 256>>>(wo, Wth + 3*EE2, Wtl + 3*EE2);

  dim3 gp(8, 64);
  convert_pack<<<2048, 256>>>(q, Inh, Inl, NSE2);
  proj_mma<0><<<gp, 256, 81920>>>(Inh, Inl, Wth + 0*EE2, Wtl + 0*EE2, bq, nullptr, Qh, Ql);
  convert_pack<<<2048, 256>>>(k, Inh, Inl, NSE2);
  proj_mma<0><<<gp, 256, 81920>>>(Inh, Inl, Wth + 1*EE2, Wtl + 1*EE2, bk, nullptr, Kh, Kl);
  convert_pack<<<2048, 256>>>(v, Inh, Inl, NSE2);
  proj_mma<2><<<gp, 256, 81920>>>(Inh, Inl, Wth + 2*EE2, Wtl + 2*EE2, bv, Vtp, nullptr, nullptr);
  convert_pack<<<2048, 256>>>(Vtp, Vth, Vtl, NSE2);

  qk_mma<<<dim3(8, 8, 128), 256, 73728>>>(mask, attn);
  pv_mma<<<dim3(8, 128), 256>>>(attn);
  proj_mma<1><<<gp, 256, 81920>>>(Oh, Ol, Wth + 3*EE2, Wtl + 3*EE2, bo, out, nullptr, nullptr);
}

// round 9
// speedup vs baseline: 1.1919x; 1.1919x over previous
#include <cuda_runtime.h>
#include <cuda_bf16.h>
#include <cstdint>

#define Nb  8
#define Ssz 1024
#define Esz 1024
#define Hn  16
#define DKs 64
#define NSE (Nb*Ssz*Esz)                 // 8388608
#define NSE2 (NSE/2)
#define EE2 (Esz*Esz/2)
#define NHSS (134217728)
#define NMW (Nb*Ssz*32)                  // mask words: 262144

// Packed bf16 hi/lo planes (word i = pair (2i, 2i+1) along k)
__device__ unsigned g_Inh[NSE2], g_Inl[NSE2];
__device__ unsigned g_Qh[NSE2], g_Ql[NSE2];
__device__ unsigned g_Kh[NSE2], g_Kl[NSE2];
__device__ unsigned g_Vth[NSE2], g_Vtl[NSE2];      // [nh][d][t/2]
__device__ unsigned g_Oh[NSE2], g_Ol[NSE2];
__device__ unsigned g_Wth[4*EE2], g_Wtl[4*EE2];
__device__ float    g_Vt[NSE];
__device__ unsigned g_mbits[NMW];                  // mask bitwords [nb][row][col/32]
__device__ float    g_attn_fb[NHSS];

#define CPA16(saddr, gptr) asm volatile("cp.async.cg.shared.global [%0], [%1], 16;\n" :: "r"(saddr), "l"(gptr))
#define CPCOMMIT() asm volatile("cp.async.commit_group;\n")
#define CPWAIT(n)  asm volatile("cp.async.wait_group %0;\n" :: "n"(n))
#define LDSM4(r0,r1,r2,r3,a) asm volatile( \
  "ldmatrix.sync.aligned.m8n8.x4.shared.b16 {%0,%1,%2,%3}, [%4];" \
  : "=r"(r0),"=r"(r1),"=r"(r2),"=r"(r3) : "r"(a))

__device__ __forceinline__ void pack2(float x, float y, unsigned& h, unsigned& l) {
  __nv_bfloat162 hh = __float22bfloat162_rn(make_float2(x, y));
  float2 f = __bfloat1622float2(hh);
  __nv_bfloat162 ll = __float22bfloat162_rn(make_float2(x - f.x, y - f.y));
  h = *reinterpret_cast<unsigned*>(&hh);
  l = *reinterpret_cast<unsigned*>(&ll);
}

__device__ __forceinline__ void mma4(float* c, const unsigned* a, unsigned b0, unsigned b1) {
  asm volatile(
      "mma.sync.aligned.m16n8k16.row.col.f32.bf16.bf16.f32 "
      "{%0,%1,%2,%3}, {%4,%5,%6,%7}, {%8,%9}, {%0,%1,%2,%3};\n"
      : "+f"(c[0]), "+f"(c[1]), "+f"(c[2]), "+f"(c[3])
      : "r"(a[0]), "r"(a[1]), "r"(a[2]), "r"(a[3]), "r"(b0), "r"(b1));
}

// 3-term split mma over CH k16-chunks; fragments via ldmatrix. NT must be even.
template <int MT, int NT, int PITCH, int CH>
__device__ __forceinline__ void compute_tile2(
    const unsigned* Ah, const unsigned* Al, const unsigned* Bh, const unsigned* Bl,
    int wm0, int wn0, int gr, int q, float (&acc)[MT][NT][4]) {
  const int lane = threadIdx.x & 31;
  const int lr  = lane & 15;           // A: row within 16-tile
  const int lkA = (lane >> 4) & 1;     // A: k-half
  const int bcol = lane & 7;           // B: col within 8-tile
  const int lkB = (lane >> 3) & 1;     // B: k-half
  const int bnt = (lane >> 4) & 1;     // B: which nt of the pair
  unsigned aAh = (unsigned)__cvta_generic_to_shared(Ah);
  unsigned aAl = (unsigned)__cvta_generic_to_shared(Al);
  unsigned aBh = (unsigned)__cvta_generic_to_shared(Bh);
  unsigned aBl = (unsigned)__cvta_generic_to_shared(Bl);
#pragma unroll
  for (int c = 0; c < CH; c++) {
    unsigned ah[MT][4], al[MT][4];
#pragma unroll
    for (int mt = 0; mt < MT; mt++) {
      unsigned off = (unsigned)(((wm0 + 16*mt + lr)*PITCH + 8*c + 4*lkA)*4);
      LDSM4(ah[mt][0], ah[mt][1], ah[mt][2], ah[mt][3], aAh + off);
      LDSM4(al[mt][0], al[mt][1], al[mt][2], al[mt][3], aAl + off);
    }
#pragma unroll
    for (int p = 0; p < NT/2; p++) {
      unsigned off = (unsigned)(((wn0 + 8*(2*p + bnt) + bcol)*PITCH + 8*c + 4*lkB)*4);
      unsigned bh0,bh1,bh2,bh3, bl0,bl1,bl2,bl3;
      LDSM4(bh0, bh1, bh2, bh3, aBh + off);
      LDSM4(bl0, bl1, bl2, bl3, aBl + off);
#pragma unroll
      for (int mt = 0; mt < MT; mt++) {
        mma4(acc[mt][2*p],   ah[mt], bh0, bh1);
        mma4(acc[mt][2*p],   ah[mt], bl0, bl1);
        mma4(acc[mt][2*p],   al[mt], bh0, bh1);
        mma4(acc[mt][2*p+1], ah[mt], bh2, bh3);
        mma4(acc[mt][2*p+1], ah[mt], bl2, bl3);
        mma4(acc[mt][2*p+1], al[mt], bh2, bh3);
      }
    }
  }
}

__global__ void convert_pack(const float* __restrict__ src,
                             unsigned* __restrict__ h, unsigned* __restrict__ l, int npairs) {
  for (int i = blockIdx.x*blockDim.x + threadIdx.x; i < npairs; i += gridDim.x*blockDim.x) {
    float2 v = ((const float2*)src)[i];
    pack2(v.x, v.y, h[i], l[i]);
  }
}

// mask int32 -> 1 bit per entry (ballot across 32 cols)
__global__ void mask_bits(const int* __restrict__ mask, unsigned* __restrict__ mb) {
  int lane = threadIdx.x & 31;
  int warp = (blockIdx.x*blockDim.x + threadIdx.x) >> 5;
  int nwarps = (gridDim.x*blockDim.x) >> 5;
  for (int w = warp; w < NMW; w += nwarps) {
    int v = mask[(size_t)w*32 + lane];
    unsigned b = __ballot_sync(0xffffffffu, v != 0);
    if (lane == 0) mb[w] = b;
  }
}

__global__ __launch_bounds__(256) void transpose_convert(
    const float* __restrict__ W, unsigned* __restrict__ Th, unsigned* __restrict__ Tl) {
  __shared__ float tile[32][33];
  int bx = blockIdx.x*32, by = blockIdx.y*32;
  int t = threadIdx.x, x = t & 31, y = t >> 5;
#pragma unroll
  for (int i = 0; i < 4; i++)
    tile[y + 8*i][x] = W[(size_t)(by + y + 8*i)*1024 + bx + x];
  __syncthreads();
#pragma unroll
  for (int j = 0; j < 2; j++) {
    int idx = t + 256*j;
    int n = idx >> 4, p = idx & 15;
    unsigned h, l;
    pack2(tile[2*p][n], tile[2*p+1][n], h, l);
    Th[(size_t)(bx + n)*512 + (by >> 1) + p] = h;
    Tl[(size_t)(bx + n)*512 + (by >> 1) + p] = l;
  }
}

__device__ __forceinline__ void proj_issue(
    unsigned sbase, const unsigned* Ah_g, const unsigned* Al_g,
    const unsigned* Bh_g, const unsigned* Bl_g, int m0, int n0, int kt2, int tid) {
#pragma unroll
  for (int j = 0; j < 2; j++) {
    int c = tid + 256*j;
    int m = c >> 2, kc = c & 3;
    unsigned d = sbase + (unsigned)((m*20 + kc*4)*4);
    size_t ga = (size_t)m*512 + kt2 + kc*4;
    CPA16(d + 0u*10240u, Ah_g + (size_t)m0*512 + ga);
    CPA16(d + 1u*10240u, Al_g + (size_t)m0*512 + ga);
    CPA16(d + 2u*10240u, Bh_g + (size_t)n0*512 + ga);
    CPA16(d + 3u*10240u, Bl_g + (size_t)n0*512 + ga);
  }
}

// ---------------------------------------------------------------------------
// Projection GEMM from planes. EPI: 0=write planes, 1=write fp32, 2=write Vt fp32
// ---------------------------------------------------------------------------
template <int EPI>
__global__ __launch_bounds__(256, 2) void proj_mma(
    const unsigned* __restrict__ Ah_g, const unsigned* __restrict__ Al_g,
    const unsigned* __restrict__ Bh_g, const unsigned* __restrict__ Bl_g,
    const float* __restrict__ bias, float* __restrict__ Cf,
    unsigned* __restrict__ Ch, unsigned* __restrict__ Cl) {
  extern __shared__ unsigned sm[];
  const int tid = threadIdx.x, wid = tid >> 5, lane = tid & 31;
  const int gr = lane >> 2, q = lane & 3;
  const int wm0 = (wid >> 2)*64, wn0 = (wid & 3)*32;
  const int m0 = blockIdx.y*128, n0 = blockIdx.x*128;
  unsigned smu = (unsigned)__cvta_generic_to_shared(sm);
  float acc[4][4][4] = {};
  proj_issue(smu, Ah_g, Al_g, Bh_g, Bl_g, m0, n0, 0, tid);
  CPCOMMIT();
  for (int t = 0; t < 32; t++) {
    if (t + 1 < 32)
      proj_issue(smu + ((t+1)&1)*40960u, Ah_g, Al_g, Bh_g, Bl_g, m0, n0, (t+1)*16, tid);
    CPCOMMIT();
    CPWAIT(1);
    __syncthreads();
    const unsigned* base = sm + (t&1)*10240;
    compute_tile2<4,4,20,2>(base, base+2560, base+5120, base+7680, wm0, wn0, gr, q, acc);
    __syncthreads();
  }
#pragma unroll
  for (int mt = 0; mt < 4; mt++) {
#pragma unroll
    for (int nt = 0; nt < 4; nt++) {
      int row = m0 + wm0 + 16*mt + gr;
      int col = n0 + wn0 + 8*nt + 2*q;
      float b0 = bias[col], b1 = bias[col+1];
      float v0 = acc[mt][nt][0] + b0, v1 = acc[mt][nt][1] + b1;
      float v2 = acc[mt][nt][2] + b0, v3 = acc[mt][nt][3] + b1;
      if (EPI == 0) {
        int w = col >> 1;
        pack2(v0, v1, Ch[(size_t)row*512 + w], Cl[(size_t)row*512 + w]);
        pack2(v2, v3, Ch[(size_t)(row+8)*512 + w], Cl[(size_t)(row+8)*512 + w]);
      } else if (EPI == 1) {
        *(float2*)&Cf[(size_t)row*1024 + col] = make_float2(v0, v1);
        *(float2*)&Cf[(size_t)(row+8)*1024 + col] = make_float2(v2, v3);
      } else {
        int nb = row >> 10, s = row & 1023;
        int h = col >> 6, d = col & 63;
        float* p = Cf + (((size_t)(nb*16 + h))*64 + d)*1024 + s;
        p[0] = v0; p[1024] = v1; p[8] = v2; p[1024 + 8] = v3;
      }
    }
  }
}

// ---------------------------------------------------------------------------
// QK^T from planes: single smem load (full K=64), dyn smem 73728B.
// Mask via precomputed bitwords: warp's 32-col span = one word.
// ---------------------------------------------------------------------------
__global__ __launch_bounds__(256, 2) void qk_mma(float* __restrict__ attn) {
  extern __shared__ unsigned sm[];
  const int tid = threadIdx.x, wid = tid >> 5, lane = tid & 31;
  const int gr = lane >> 2, q = lane & 3;
  const int wm0 = (wid >> 2)*64, wn0 = (wid & 3)*32;
  const int t0 = blockIdx.x*128, m0 = blockIdx.y*128;
  const int nh = blockIdx.z, nb = nh >> 4, h = nh & 15;
  unsigned smu = (unsigned)__cvta_generic_to_shared(sm);
  const size_t qoff = (size_t)(nb*1024 + m0)*512 + h*32;
  const size_t koff = (size_t)(nb*1024 + t0)*512 + h*32;
#pragma unroll
  for (int j = 0; j < 4; j++) {
    int c = tid + 256*j;
    int m = c >> 3, kc = c & 7;
    unsigned d = smu + (unsigned)((m*36 + kc*4)*4);
    size_t ga = (size_t)m*512 + kc*4;
    CPA16(d + 0u*18432u, g_Qh + qoff + ga);
    CPA16(d + 1u*18432u, g_Ql + qoff + ga);
    CPA16(d + 2u*18432u, g_Kh + koff + ga);
    CPA16(d + 3u*18432u, g_Kl + koff + ga);
  }
  CPCOMMIT();
  CPWAIT(0);
  __syncthreads();
  float acc[4][4][4] = {};
  compute_tile2<4,4,36,4>(sm, sm+4608, sm+9216, sm+13824, wm0, wn0, gr, q, acc);
  const int wcol = (t0 + wn0) >> 5;
#pragma unroll
  for (int mt = 0; mt < 4; mt++) {
    int row = m0 + wm0 + 16*mt + gr;
    unsigned w0 = g_mbits[((size_t)nb*1024 + row)*32 + wcol];
    unsigned w1 = g_mbits[((size_t)nb*1024 + row + 8)*32 + wcol];
#pragma unroll
    for (int nt = 0; nt < 4; nt++) {
      int t = t0 + wn0 + 8*nt + 2*q;
      int b = 8*nt + 2*q;
      float2 v0, v1;
      v0.x = ((w0 >> b) & 1)       ? -1e9f : acc[mt][nt][0]*0.125f;
      v0.y = ((w0 >> (b+1)) & 1)   ? -1e9f : acc[mt][nt][1]*0.125f;
      v1.x = ((w1 >> b) & 1)       ? -1e9f : acc[mt][nt][2]*0.125f;
      v1.y = ((w1 >> (b+1)) & 1)   ? -1e9f : acc[mt][nt][3]*0.125f;
      *(float2*)&attn[((size_t)nh*1024 + row)*1024 + t] = v0;
      *(float2*)&attn[((size_t)nh*1024 + row + 8)*1024 + t] = v1;
    }
  }
}

// ---------------------------------------------------------------------------
// In-place row softmax, rows of 1024.
// ---------------------------------------------------------------------------
__global__ __launch_bounds__(256) void softmax_kernel(float* __restrict__ attn) {
  __shared__ float red[8];
  const int tid = threadIdx.x;
  size_t rowIdx = (size_t)blockIdx.y*1024 + blockIdx.x;
  float* row = attn + rowIdx*1024;
  float4 v = ((float4*)row)[tid];
  float m = fmaxf(fmaxf(v.x, v.y), fmaxf(v.z, v.w));
#pragma unroll
  for (int o = 16; o > 0; o >>= 1) m = fmaxf(m, __shfl_xor_sync(0xffffffffu, m, o));
  if ((tid & 31) == 0) red[tid >> 5] = m;
  __syncthreads();
  m = fmaxf(fmaxf(fmaxf(red[0], red[1]), fmaxf(red[2], red[3])),
            fmaxf(fmaxf(red[4], red[5]), fmaxf(red[6], red[7])));
  float4 e;
  e.x = __expf(v.x - m); e.y = __expf(v.y - m);
  e.z = __expf(v.z - m); e.w = __expf(v.w - m);
  float s = (e.x + e.y) + (e.z + e.w);
#pragma unroll
  for (int o = 16; o > 0; o >>= 1) s += __shfl_xor_sync(0xffffffffu, s, o);
  __syncthreads();
  if ((tid & 31) == 0) red[tid >> 5] = s;
  __syncthreads();
  s = ((red[0]+red[1]) + (red[2]+red[3])) + ((red[4]+red[5]) + (red[6]+red[7]));
  float inv = 1.0f / s;
  e.x *= inv; e.y *= inv; e.z *= inv; e.w *= inv;
  ((float4*)row)[tid] = e;
}

// ---------------------------------------------------------------------------
// PV: A = softmax P (fp32, inline split), B = Vt planes. Writes O planes.
// ---------------------------------------------------------------------------
__global__ __launch_bounds__(256, 2) void pv_mma(const float* __restrict__ attn) {
  __shared__ unsigned Ah[2560], Al[2560], Bh[1280], Bl[1280];
  const int tid = threadIdx.x, wid = tid >> 5, lane = tid & 31;
  const int gr = lane >> 2, q = lane & 3;
  const int wm0 = (wid >> 2)*64, wn0 = (wid & 3)*16;
  const int m0 = blockIdx.x*128;
  const int nh = blockIdx.y, nb = nh >> 4, h = nh & 15;
  const float* P = attn + (size_t)nh*1024*1024 + (size_t)m0*1024;
  float acc[4][2][4] = {};
  for (int kt = 0; kt < 1024; kt += 32) {
#pragma unroll
    for (int j = 0; j < 4; j++) {
      int e = tid + 256*j;
      int m = e >> 3, kq = e & 7;
      float4 v = *(const float4*)(P + (size_t)m*1024 + kt + 4*kq);
      unsigned h01, h23, l01, l23;
      pack2(v.x, v.y, h01, l01);
      pack2(v.z, v.w, h23, l23);
      int base = m*20 + 2*kq;
      Ah[base]=h01; Ah[base+1]=h23; Al[base]=l01; Al[base+1]=l23;
    }
    {
      int m = tid >> 2, kc = tid & 3;
      if (m < 64) {
        size_t src = (size_t)(nh*64 + m)*512 + (kt >> 1) + kc*4;
        *(uint4*)&Bh[m*20 + kc*4] = *(const uint4*)&g_Vth[src];
        *(uint4*)&Bl[m*20 + kc*4] = *(const uint4*)&g_Vtl[src];
      }
    }
    __syncthreads();
    compute_tile2<4,2,20,2>(Ah, Al, Bh, Bl, wm0, wn0, gr, q, acc);
    __syncthreads();
  }
#pragma unroll
  for (int mt = 0; mt < 4; mt++) {
#pragma unroll
    for (int nt = 0; nt < 2; nt++) {
      int s = m0 + wm0 + 16*mt + gr;
      int col = h*64 + wn0 + 8*nt + 2*q;
      int w = col >> 1;
      size_t r0 = (size_t)(nb*1024 + s)*512 + w;
      size_t r1 = (size_t)(nb*1024 + s + 8)*512 + w;
      pack2(acc[mt][nt][0], acc[mt][nt][1], g_Oh[r0], g_Ol[r0]);
      pack2(acc[mt][nt][2], acc[mt][nt][3], g_Oh[r1], g_Ol[r1]);
    }
  }
}

// ---------------------------------------------------------------------------
extern "C" void kernel_launch(void* const* d_in, const int* in_sizes, int n_in,
                              void* d_out, int out_size) {
  const float* q  = (const float*)d_in[0];
  const float* k  = (const float*)d_in[1];
  const float* v  = (const float*)d_in[2];
  const int*   mask = (const int*)d_in[3];
  const float* wq = (const float*)d_in[4];
  const float* bq = (const float*)d_in[5];
  const float* wk = (const float*)d_in[6];
  const float* bk = (const float*)d_in[7];
  const float* wv = (const float*)d_in[8];
  const float* bv = (const float*)d_in[9];
  const float* wo = (const float*)d_in[10];
  const float* bo = (const float*)d_in[11];
  float* out = (float*)d_out;

  static bool attr_done = false;
  if (!attr_done) {
    cudaFuncSetAttribute(proj_mma<0>, cudaFuncAttributeMaxDynamicSharedMemorySize, 81920);
    cudaFuncSetAttribute(proj_mma<1>, cudaFuncAttributeMaxDynamicSharedMemorySize, 81920);
    cudaFuncSetAttribute(proj_mma<2>, cudaFuncAttributeMaxDynamicSharedMemorySize, 81920);
    cudaFuncSetAttribute(qk_mma, cudaFuncAttributeMaxDynamicSharedMemorySize, 73728);
    attr_done = true;
  }

  unsigned *Inh, *Inl, *Qh, *Ql, *Kh, *Kl, *Vth, *Vtl, *Oh, *Ol, *Wth, *Wtl, *mb;
  float *Vtp, *attn;
  cudaGetSymbolAddress((void**)&Inh, g_Inh);  cudaGetSymbolAddress((void**)&Inl, g_Inl);
  cudaGetSymbolAddress((void**)&Qh, g_Qh);    cudaGetSymbolAddress((void**)&Ql, g_Ql);
  cudaGetSymbolAddress((void**)&Kh, g_Kh);    cudaGetSymbolAddress((void**)&Kl, g_Kl);
  cudaGetSymbolAddress((void**)&Vth, g_Vth);  cudaGetSymbolAddress((void**)&Vtl, g_Vtl);
  cudaGetSymbolAddress((void**)&Oh, g_Oh);    cudaGetSymbolAddress((void**)&Ol, g_Ol);
  cudaGetSymbolAddress((void**)&Wth, g_Wth);  cudaGetSymbolAddress((void**)&Wtl, g_Wtl);
  cudaGetSymbolAddress((void**)&Vtp, g_Vt);
  cudaGetSymbolAddress((void**)&mb, g_mbits);
  if ((long long)out_size >= (long long)NSE + (long long)NHSS) {
    attn = out + NSE;
  } else {
    cudaGetSymbolAddress((void**)&attn, g_attn_fb);
  }

  dim3 tg(32, 32);
  transpose_convert<<<tg, 256>>>(wq, Wth + 0*EE2, Wtl + 0*EE2);
  transpose_convert<<<tg, 256>>>(wk, Wth + 1*EE2, Wtl + 1*EE2);
  transpose_convert<<<tg, 256>>>(wv, Wth + 2*EE2, Wtl + 2*EE2);
  transpose_convert<<<tg, 256>>>(wo, Wth + 3*EE2, Wtl + 3*EE2);
  mask_bits<<<1024, 256>>>(mask, mb);

  dim3 gp(8, 64);
  convert_pack<<<2048, 256>>>(q, Inh, Inl, NSE2);
  proj_mma<0><<<gp, 256, 81920>>>(Inh, Inl, Wth + 0*EE2, Wtl + 0*EE2, bq, nullptr, Qh, Ql);
  convert_pack<<<2048, 256>>>(k, Inh, Inl, NSE2);
  proj_mma<0><<<gp, 256, 81920>>>(Inh, Inl, Wth + 1*EE2, Wtl + 1*EE2, bk, nullptr, Kh, Kl);
  convert_pack<<<2048, 256>>>(v, Inh, Inl, NSE2);
  proj_mma<2><<<gp, 256, 81920>>>(Inh, Inl, Wth + 2*EE2, Wtl + 2*EE2, bv, Vtp, nullptr, nullptr);
  convert_pack<<<2048, 256>>>(Vtp, Vth, Vtl, NSE2);

  qk_mma<<<dim3(8, 8, 128), 256, 73728>>>(attn);
  softmax_kernel<<<dim3(1024, 128), 256>>>(attn);
  pv_mma<<<dim3(8, 128), 256>>>(attn);
  proj_mma<1><<<gp, 256, 81920>>>(Oh, Ol, Wth + 3*EE2, Wtl + 3*EE2, bo, out, nullptr, nullptr);
}

// round 12
// speedup vs baseline: 1.4627x; 1.2272x over previous
#include <cuda_runtime.h>
#include <cuda_bf16.h>
#include <cstdint>

#define Nb  8
#define Ssz 1024
#define Esz 1024
#define Hn  16
#define DKs 64
#define NSE (Nb*Ssz*Esz)                 // 8388608
#define NHSS (134217728)
#define NMW (Nb*Ssz*32)                  // mask words: 262144

// fp32 buffers (tf32-rounded values stored as fp32)
__device__ float g_In[NSE];              // rounded projection input
__device__ float g_Q[NSE], g_K[NSE];     // rounded Q,K [n,s,h,d]
__device__ float g_Vt[NSE];              // rounded V transposed [nh][d][t]
__device__ float g_O[NSE];               // rounded attention output
__device__ float g_Wt[4*Esz*Esz];        // rounded transposed weights [n][k]
__device__ unsigned g_mbits[NMW];        // mask bitwords [nb][row][col/32]
__device__ float g_attn_fb[NHSS];

#define CPA16(saddr, gptr) asm volatile("cp.async.cg.shared.global [%0], [%1], 16;\n" :: "r"(saddr), "l"(gptr))
#define CPCOMMIT() asm volatile("cp.async.commit_group;\n")
#define CPWAIT(n)  asm volatile("cp.async.wait_group %0;\n" :: "n"(n))
#define LDSM4(r0,r1,r2,r3,a) asm volatile( \
  "ldmatrix.sync.aligned.m8n8.x4.shared.b16 {%0,%1,%2,%3}, [%4];" \
  : "=r"(r0),"=r"(r1),"=r"(r2),"=r"(r3) : "r"(a))
#define LDSM2(r0,r1,a) asm volatile( \
  "ldmatrix.sync.aligned.m8n8.x2.shared.b16 {%0,%1}, [%2];" \
  : "=r"(r0),"=r"(r1) : "r"(a))

__device__ __forceinline__ float rtf(float x) {
  unsigned u;
  asm("cvt.rna.tf32.f32 %0, %1;" : "=r"(u) : "f"(x));
  return __uint_as_float(u);
}

__device__ __forceinline__ void mma8(float* c, const unsigned* a, unsigned b0, unsigned b1) {
  asm volatile(
      "mma.sync.aligned.m16n8k8.row.col.f32.tf32.tf32.f32 "
      "{%0,%1,%2,%3}, {%4,%5,%6,%7}, {%8,%9}, {%0,%1,%2,%3};\n"
      : "+f"(c[0]), "+f"(c[1]), "+f"(c[2]), "+f"(c[3])
      : "r"(a[0]), "r"(a[1]), "r"(a[2]), "r"(a[3]), "r"(b0), "r"(b1));
}

// tf32 warp-tile compute over CH k8-chunks. A,B fp32 smem tiles, pitch in words.
template <int MT, int NT, int PITCH, int CH>
__device__ __forceinline__ void compute_tf(
    const float* A, const float* B, int wm0, int wn0, float (&acc)[MT][NT][4]) {
  const int lane = threadIdx.x & 31;
  unsigned aA = (unsigned)__cvta_generic_to_shared(A);
  unsigned aB = (unsigned)__cvta_generic_to_shared(B);
#pragma unroll
  for (int c = 0; c < CH; c++) {
    unsigned a[MT][4];
#pragma unroll
    for (int mt = 0; mt < MT; mt++) {
      unsigned off = (unsigned)((((wm0 + 16*mt + (lane & 15))*PITCH) + c*8 + (lane >> 4)*4)*4);
      LDSM4(a[mt][0], a[mt][1], a[mt][2], a[mt][3], aA + off);
    }
#pragma unroll
    for (int nt = 0; nt < NT; nt++) {
      unsigned off = (unsigned)((((wn0 + 8*nt + (lane & 7))*PITCH) + c*8 + ((lane >> 3) & 1)*4)*4);
      unsigned b0, b1;
      LDSM2(b0, b1, aB + off);
#pragma unroll
      for (int mt = 0; mt < MT; mt++) mma8(acc[mt][nt], a[mt], b0, b1);
    }
  }
}

// round fp32 -> tf32-valued fp32 (grid-stride float4)
__global__ void round_tf32(const float* __restrict__ src, float* __restrict__ dst, int n4) {
  for (int i = blockIdx.x*blockDim.x + threadIdx.x; i < n4; i += gridDim.x*blockDim.x) {
    float4 v = ((const float4*)src)[i];
    v.x = rtf(v.x); v.y = rtf(v.y); v.z = rtf(v.z); v.w = rtf(v.w);
    ((float4*)dst)[i] = v;
  }
}

// W[k][n] -> Wt[n][k], rounded
__global__ __launch_bounds__(256) void transpose_round(
    const float* __restrict__ W, float* __restrict__ Wt) {
  __shared__ float tile[32][33];
  int bx = blockIdx.x*32, by = blockIdx.y*32;
  int t = threadIdx.x, x = t & 31, y = t >> 5;
#pragma unroll
  for (int i = 0; i < 4; i++)
    tile[y + 8*i][x] = W[(size_t)(by + y + 8*i)*1024 + bx + x];
  __syncthreads();
#pragma unroll
  for (int i = 0; i < 4; i++)
    Wt[(size_t)(bx + y + 8*i)*1024 + by + x] = rtf(tile[x][y + 8*i]);
}

// mask int32 -> 1 bit per entry
__global__ void mask_bits(const int* __restrict__ mask, unsigned* __restrict__ mb) {
  int lane = threadIdx.x & 31;
  int warp = (blockIdx.x*blockDim.x + threadIdx.x) >> 5;
  int nwarps = (gridDim.x*blockDim.x) >> 5;
  for (int w = warp; w < NMW; w += nwarps) {
    int v = mask[(size_t)w*32 + lane];
    unsigned b = __ballot_sync(0xffffffffu, v != 0);
    if (lane == 0) mb[w] = b;
  }
}

// load 128x32 fp32 tile into stage (pitch 36 words)
__device__ __forceinline__ void proj_issue(
    unsigned st, const float* __restrict__ A, const float* __restrict__ B,
    int kt, int tid) {
#pragma unroll
  for (int j = 0; j < 4; j++) {
    int c = tid + 256*j;
    int row = c >> 3, ch = c & 7;
    unsigned d = st + (unsigned)((row*36 + ch*4)*4);
    CPA16(d,          A + (size_t)row*1024 + kt + ch*4);
    CPA16(d + 18432u, B + (size_t)row*1024 + kt + ch*4);
  }
}

// ---------------------------------------------------------------------------
// Projection GEMM (tf32). EPI: 0 = rounded fp32 (Q/K), 1 = plain fp32 out,
// 2 = rounded Vt-transposed.  CTA 128x128, 2-stage cp.async, dyn smem 73728.
// ---------------------------------------------------------------------------
template <int EPI>
__global__ __launch_bounds__(256, 2) void proj_tf(
    const float* __restrict__ Af, const float* __restrict__ Wt,
    const float* __restrict__ bias, float* __restrict__ Cf) {
  extern __shared__ float sm[];
  const int tid = threadIdx.x, wid = tid >> 5, lane = tid & 31;
  const int gr = lane >> 2, q = lane & 3;
  const int wm0 = (wid >> 2)*64, wn0 = (wid & 3)*32;
  const int m0 = blockIdx.y*128, n0 = blockIdx.x*128;
  unsigned smu = (unsigned)__cvta_generic_to_shared(sm);
  const float* A = Af + (size_t)m0*1024;
  const float* B = Wt + (size_t)n0*1024;
  float acc[4][4][4] = {};
  proj_issue(smu, A, B, 0, tid);
  CPCOMMIT();
  for (int t = 0; t < 32; t++) {
    if (t + 1 < 32)
      proj_issue(smu + ((t+1)&1)*36864u, A, B, (t+1)*32, tid);
    CPCOMMIT();
    CPWAIT(1);
    __syncthreads();
    const float* base = sm + (t&1)*9216;
    compute_tf<4,4,36,4>(base, base + 4608, wm0, wn0, acc);
    __syncthreads();
  }
#pragma unroll
  for (int mt = 0; mt < 4; mt++) {
#pragma unroll
    for (int nt = 0; nt < 4; nt++) {
      int row = m0 + wm0 + 16*mt + gr;
      int col = n0 + wn0 + 8*nt + 2*q;
      float b0 = bias[col], b1 = bias[col+1];
      float v0 = acc[mt][nt][0] + b0, v1 = acc[mt][nt][1] + b1;
      float v2 = acc[mt][nt][2] + b0, v3 = acc[mt][nt][3] + b1;
      if (EPI == 0) {
        *(float2*)&Cf[(size_t)row*1024 + col]     = make_float2(rtf(v0), rtf(v1));
        *(float2*)&Cf[(size_t)(row+8)*1024 + col] = make_float2(rtf(v2), rtf(v3));
      } else if (EPI == 1) {
        *(float2*)&Cf[(size_t)row*1024 + col]     = make_float2(v0, v1);
        *(float2*)&Cf[(size_t)(row+8)*1024 + col] = make_float2(v2, v3);
      } else {
        int nb = row >> 10, s = row & 1023;
        int h = col >> 6, d = col & 63;
        float* p = Cf + (((size_t)(nb*16 + h))*64 + d)*1024 + s;
        p[0] = rtf(v0); p[1024] = rtf(v1); p[8] = rtf(v2); p[1024 + 8] = rtf(v3);
      }
    }
  }
}

// ---------------------------------------------------------------------------
// QK^T (tf32): full K=64 in smem (pitch 68), bitmask epilogue. dyn smem 69632.
// ---------------------------------------------------------------------------
__global__ __launch_bounds__(256, 2) void qk_tf(float* __restrict__ attn) {
  extern __shared__ float sm[];
  const int tid = threadIdx.x, wid = tid >> 5, lane = tid & 31;
  const int gr = lane >> 2, q = lane & 3;
  const int wm0 = (wid >> 2)*64, wn0 = (wid & 3)*32;
  const int t0 = blockIdx.x*128, m0 = blockIdx.y*128;
  const int nh = blockIdx.z, nb = nh >> 4, h = nh & 15;
  unsigned smu = (unsigned)__cvta_generic_to_shared(sm);
  const float* Qb = g_Q + (size_t)(nb*1024 + m0)*1024 + h*64;
  const float* Kb = g_K + (size_t)(nb*1024 + t0)*1024 + h*64;
#pragma unroll
  for (int j = 0; j < 8; j++) {
    int c = tid + 256*j;
    int row = c >> 4, ch = c & 15;
    unsigned d = smu + (unsigned)((row*68 + ch*4)*4);
    CPA16(d,          Qb + (size_t)row*1024 + ch*4);
    CPA16(d + 34816u, Kb + (size_t)row*1024 + ch*4);
  }
  CPCOMMIT();
  CPWAIT(0);
  __syncthreads();
  float acc[4][4][4] = {};
  compute_tf<4,4,68,8>(sm, sm + 8704, wm0, wn0, acc);
  const int wcol = (t0 + wn0) >> 5;
#pragma unroll
  for (int mt = 0; mt < 4; mt++) {
    int row = m0 + wm0 + 16*mt + gr;
    unsigned w0 = g_mbits[((size_t)nb*1024 + row)*32 + wcol];
    unsigned w1 = g_mbits[((size_t)nb*1024 + row + 8)*32 + wcol];
#pragma unroll
    for (int nt = 0; nt < 4; nt++) {
      int t = t0 + wn0 + 8*nt + 2*q;
      int b = 8*nt + 2*q;
      float2 v0, v1;
      v0.x = ((w0 >> b) & 1)     ? -1e9f : acc[mt][nt][0]*0.125f;
      v0.y = ((w0 >> (b+1)) & 1) ? -1e9f : acc[mt][nt][1]*0.125f;
      v1.x = ((w1 >> b) & 1)     ? -1e9f : acc[mt][nt][2]*0.125f;
      v1.y = ((w1 >> (b+1)) & 1) ? -1e9f : acc[mt][nt][3]*0.125f;
      *(float2*)&attn[((size_t)nh*1024 + row)*1024 + t] = v0;
      *(float2*)&attn[((size_t)nh*1024 + row + 8)*1024 + t] = v1;
    }
  }
}

// ---------------------------------------------------------------------------
// In-place row softmax, rows of 1024.
// ---------------------------------------------------------------------------
__global__ __launch_bounds__(256) void softmax_kernel(float* __restrict__ attn) {
  __shared__ float red[8];
  const int tid = threadIdx.x;
  size_t rowIdx = (size_t)blockIdx.y*1024 + blockIdx.x;
  float* row = attn + rowIdx*1024;
  float4 v = ((float4*)row)[tid];
  float m = fmaxf(fmaxf(v.x, v.y), fmaxf(v.z, v.w));
#pragma unroll
  for (int o = 16; o > 0; o >>= 1) m = fmaxf(m, __shfl_xor_sync(0xffffffffu, m, o));
  if ((tid & 31) == 0) red[tid >> 5] = m;
  __syncthreads();
  m = fmaxf(fmaxf(fmaxf(red[0], red[1]), fmaxf(red[2], red[3])),
            fmaxf(fmaxf(red[4], red[5]), fmaxf(red[6], red[7])));
  float4 e;
  e.x = __expf(v.x - m); e.y = __expf(v.y - m);
  e.z = __expf(v.z - m); e.w = __expf(v.w - m);
  float s = (e.x + e.y) + (e.z + e.w);
#pragma unroll
  for (int o = 16; o > 0; o >>= 1) s += __shfl_xor_sync(0xffffffffu, s, o);
  __syncthreads();
  if ((tid & 31) == 0) red[tid >> 5] = s;
  __syncthreads();
  s = ((red[0]+red[1]) + (red[2]+red[3])) + ((red[4]+red[5]) + (red[6]+red[7]));
  float inv = 1.0f / s;
  e.x *= inv; e.y *= inv; e.z *= inv; e.w *= inv;
  ((float4*)row)[tid] = e;
}

// ---------------------------------------------------------------------------
// PV (tf32): A = softmax P (rounded inline), B = Vt. Writes rounded O fp32.
// ---------------------------------------------------------------------------
__global__ __launch_bounds__(256, 2) void pv_tf(const float* __restrict__ attn) {
  __shared__ float As[4608];   // 128 x pitch36
  __shared__ float Bs[2304];   // 64  x pitch36
  const int tid = threadIdx.x, wid = tid >> 5, lane = tid & 31;
  const int gr = lane >> 2, q = lane & 3;
  const int wm0 = (wid >> 2)*64, wn0 = (wid & 3)*16;
  const int m0 = blockIdx.x*128;
  const int nh = blockIdx.y, nb = nh >> 4, h = nh & 15;
  const float* P = attn + (size_t)nh*1024*1024 + (size_t)m0*1024;
  const float* Vb = g_Vt + (size_t)nh*64*1024;
  float acc[4][2][4] = {};
  for (int kt = 0; kt < 1024; kt += 32) {
#pragma unroll
    for (int j = 0; j < 4; j++) {
      int e = tid + 256*j;
      int m = e >> 3, kq = e & 7;
      float4 v = *(const float4*)(P + (size_t)m*1024 + kt + 4*kq);
      v.x = rtf(v.x); v.y = rtf(v.y); v.z = rtf(v.z); v.w = rtf(v.w);
      *(float4*)&As[m*36 + 4*kq] = v;
    }
#pragma unroll
    for (int j = 0; j < 2; j++) {
      int e = tid + 256*j;
      int m = e >> 3, kq = e & 7;
      if (m < 64)
        *(float4*)&Bs[m*36 + 4*kq] = *(const float4*)(Vb + (size_t)m*1024 + kt + 4*kq);
    }
    __syncthreads();
    compute_tf<4,2,36,4>(As, Bs, wm0, wn0, acc);
    __syncthreads();
  }
#pragma unroll
  for (int mt = 0; mt < 4; mt++) {
#pragma unroll
    for (int nt = 0; nt < 2; nt++) {
      int s = m0 + wm0 + 16*mt + gr;
      int col = h*64 + wn0 + 8*nt + 2*q;
      *(float2*)&g_O[(size_t)(nb*1024 + s)*1024 + col] =
          make_float2(rtf(acc[mt][nt][0]), rtf(acc[mt][nt][1]));
      *(float2*)&g_O[(size_t)(nb*1024 + s + 8)*1024 + col] =
          make_float2(rtf(acc[mt][nt][2]), rtf(acc[mt][nt][3]));
    }
  }
}

// ---------------------------------------------------------------------------
extern "C" void kernel_launch(void* const* d_in, const int* in_sizes, int n_in,
                              void* d_out, int out_size) {
  const float* q  = (const float*)d_in[0];
  const float* k  = (const float*)d_in[1];
  const float* v  = (const float*)d_in[2];
  const int*   mask = (const int*)d_in[3];
  const float* wq = (const float*)d_in[4];
  const float* bq = (const float*)d_in[5];
  const float* wk = (const float*)d_in[6];
  const float* bk = (const float*)d_in[7];
  const float* wv = (const float*)d_in[8];
  const float* bv = (const float*)d_in[9];
  const float* wo = (const float*)d_in[10];
  const float* bo = (const float*)d_in[11];
  float* out = (float*)d_out;

  static bool attr_done = false;
  if (!attr_done) {
    cudaFuncSetAttribute(proj_tf<0>, cudaFuncAttributeMaxDynamicSharedMemorySize, 73728);
    cudaFuncSetAttribute(proj_tf<1>, cudaFuncAttributeMaxDynamicSharedMemorySize, 73728);
    cudaFuncSetAttribute(proj_tf<2>, cudaFuncAttributeMaxDynamicSharedMemorySize, 73728);
    cudaFuncSetAttribute(qk_tf, cudaFuncAttributeMaxDynamicSharedMemorySize, 69632);
    attr_done = true;
  }

  float *In, *Qp, *Kp, *Vtp, *Op, *Wtp, *attn;
  unsigned* mb;
  cudaGetSymbolAddress((void**)&In, g_In);
  cudaGetSymbolAddress((void**)&Qp, g_Q);
  cudaGetSymbolAddress((void**)&Kp, g_K);
  cudaGetSymbolAddress((void**)&Vtp, g_Vt);
  cudaGetSymbolAddress((void**)&Op, g_O);
  cudaGetSymbolAddress((void**)&Wtp, g_Wt);
  cudaGetSymbolAddress((void**)&mb, g_mbits);
  if ((long long)out_size >= (long long)NSE + (long long)NHSS) {
    attn = out + NSE;
  } else {
    cudaGetSymbolAddress((void**)&attn, g_attn_fb);
  }
  float* Wtq = Wtp;
  float* Wtk = Wtp + 1*Esz*Esz;
  float* Wtv = Wtp + 2*Esz*Esz;
  float* Wto = Wtp + 3*Esz*Esz;

  dim3 tg(32, 32);
  transpose_round<<<tg, 256>>>(wq, Wtq);
  transpose_round<<<tg, 256>>>(wk, Wtk);
  transpose_round<<<tg, 256>>>(wv, Wtv);
  transpose_round<<<tg, 256>>>(wo, Wto);
  mask_bits<<<1024, 256>>>(mask, mb);

  dim3 gp(8, 64);
  round_tf32<<<2048, 256>>>(q, In, NSE/4);
  proj_tf<0><<<gp, 256, 73728>>>(In, Wtq, bq, Qp);
  round_tf32<<<2048, 256>>>(k, In, NSE/4);
  proj_tf<0><<<gp, 256, 73728>>>(In, Wtk, bk, Kp);
  round_tf32<<<2048, 256>>>(v, In, NSE/4);
  proj_tf<2><<<gp, 256, 73728>>>(In, Wtv, bv, Vtp);

  qk_tf<<<dim3(8, 8, 128), 256, 69632>>>(attn);
  softmax_kernel<<<dim3(1024, 128), 256>>>(attn);
  pv_tf<<<dim3(8, 128), 256>>>(attn);
  proj_tf<1><<<gp, 256, 73728>>>(Op, Wto, bo, out);
}